// round 1
// baseline (speedup 1.0000x reference)
#include <cuda_runtime.h>
#include <cstdint>

// Packed dual-FMA (Blackwell f32x2) — only reachable via PTX.
#define FMA_X2(d, a, b, c) \
    asm("fma.rn.f32x2 %0, %1, %2, %3;" : "=l"(d) : "l"(a), "l"(b), "l"(c))

constexpr int T_LEN  = 4000;   // samples per row
constexpr int NT     = 413;    // taps
constexpr int NE     = 412;    // n_edge
constexpr int OFF    = 206;    // x_ext base offset: out[t] = sum_k h[412-k]*x_ext[t+206+k]
constexpr int S_LEN  = T_LEN + NT;   // 4413 valid staged samples
constexpr int S_ALLOC = 4424;        // padded with zeros (compute touches up to 4415)
constexpr int K_PAD  = 416;          // taps padded to multiple of 8 (zeros)
constexpr int THREADS = 512;
constexpr int NROWS  = 64 * 64;      // 4096 rows

// reflect_limited extension value at x_ext index e, e in [206, 4618]
__device__ __forceinline__ float xext_val(const float* __restrict__ xr, int e) {
    if (e < NE)           return 2.0f * xr[0]         - xr[NE - e];          // left pad
    if (e < NE + T_LEN)   return xr[e - NE];                                 // body
    return 2.0f * xr[T_LEN - 1] - xr[2 * T_LEN - 2 + NE - e];                // right pad (8410-e)
}

__global__ void __launch_bounds__(THREADS, 2)
fir_bandpass_kernel(const float* __restrict__ x,
                    const float* __restrict__ h,
                    float* __restrict__ out)
{
    __shared__ float2 s2[S_ALLOC];   // interleaved pair of rows, extended signal
    __shared__ float2 h2[K_PAD];     // reversed taps, duplicated into both lanes

    const int tid = threadIdx.x;
    const size_t row0 = (size_t)blockIdx.x * 2;
    const float* xr0 = x + row0 * T_LEN;
    const float* xr1 = xr0 + T_LEN;

    // Stage extended signal for both rows (coalesced in the body region).
    for (int i = tid; i < S_ALLOC; i += THREADS) {
        float2 v = make_float2(0.0f, 0.0f);
        if (i < S_LEN) {
            int e = i + OFF;
            v.x = xext_val(xr0, e);
            v.y = xext_val(xr1, e);
        }
        s2[i] = v;
    }
    // Stage reversed taps (h is linear-phase; use explicit reversal, no symmetry assumption).
    for (int k = tid; k < K_PAD; k += THREADS) {
        float hv = (k < NT) ? h[NT - 1 - k] : 0.0f;
        h2[k] = make_float2(hv, hv);
    }
    __syncthreads();

    const int t0 = tid * 8;
    if (t0 < T_LEN) {
        const unsigned long long* su =
            reinterpret_cast<const unsigned long long*>(s2) + t0;
        const unsigned long long* hu =
            reinterpret_cast<const unsigned long long*>(h2);

        unsigned long long acc[8] = {0, 0, 0, 0, 0, 0, 0, 0};
        unsigned long long w[8];
        #pragma unroll
        for (int r = 0; r < 8; r++) w[r] = su[r];

        // Rolled outer loop (52 iters) keeps the body ~1.4KB SASS (fits L0 I$).
        #pragma unroll 1
        for (int k = 0; k < K_PAD; k += 8) {
            #pragma unroll
            for (int u = 0; u < 8; u++) {
                unsigned long long hk = hu[k + u];
                // invariant: w[(u+j)&7] == s[t0 + k + u + j], j=0..7
                #pragma unroll
                for (int r = 0; r < 8; r++)
                    FMA_X2(acc[r], hk, w[(u + r) & 7], acc[r]);
                w[u] = su[k + u + 8];   // refill consumed slot for next step
            }
        }

        float2 res[8];
        #pragma unroll
        for (int r = 0; r < 8; r++)
            res[r] = *reinterpret_cast<float2*>(&acc[r]);

        float* o0 = out + row0 * T_LEN + t0;
        float* o1 = o0 + T_LEN;
        float4 v0 = make_float4(res[0].x, res[1].x, res[2].x, res[3].x);
        float4 v1 = make_float4(res[4].x, res[5].x, res[6].x, res[7].x);
        float4 v2 = make_float4(res[0].y, res[1].y, res[2].y, res[3].y);
        float4 v3 = make_float4(res[4].y, res[5].y, res[6].y, res[7].y);
        reinterpret_cast<float4*>(o0)[0] = v0;
        reinterpret_cast<float4*>(o0)[1] = v1;
        reinterpret_cast<float4*>(o1)[0] = v2;
        reinterpret_cast<float4*>(o1)[1] = v3;
    }
}

extern "C" void kernel_launch(void* const* d_in, const int* in_sizes, int n_in,
                              void* d_out, int out_size)
{
    const float* x = (const float*)d_in[0];   // [64, 64, 4000] float32
    const float* h = (const float*)d_in[1];   // [413] float32
    float* out = (float*)d_out;               // [64, 64, 4000] float32

    fir_bandpass_kernel<<<NROWS / 2, THREADS>>>(x, h, out);
}

// round 2
// speedup vs baseline: 2.3763x; 2.3763x over previous
#include <cuda_runtime.h>
#include <cstdint>

// Packed dual-FMA (Blackwell f32x2) — only reachable via PTX.
#define FMA_X2(d, a, b, c) \
    asm("fma.rn.f32x2 %0, %1, %2, %3;" : "=l"(d) : "l"(a), "l"(b), "l"(c))

constexpr int T_LEN  = 4000;   // samples per row
constexpr int NT     = 413;    // taps
constexpr int NE     = 412;    // n_edge
constexpr int OFF    = 206;    // x_ext base: out[t] = sum_k h_rev[k]*x_ext[t+206+k]
constexpr int S_LEN  = T_LEN + NT;   // 4413 valid staged samples
constexpr int S_ALLOC = 4416;        // multiple of 16 (swizzle block), >= max index 4415
constexpr int K_PAD  = 416;          // taps padded to multiple of 16 (zeros)
constexpr int W      = 16;           // register window / outputs per thread
constexpr int THREADS = 256;
constexpr int NROWS  = 64 * 64;      // 4096 rows

// XOR swizzle on float2-granule index: conflict-free for lane stride of 16
// granules (reads) AND stride-1 (staging writes). Bijective within each
// 16-granule block, so zero-fill of [S_LEN, S_ALLOC) still covers everything.
__device__ __forceinline__ int SW2(int g) { return g ^ ((g >> 4) & 15); }

// reflect_limited extension value at x_ext index e, e in [206, 4618]
__device__ __forceinline__ float xext_val(const float* __restrict__ xr, int e) {
    if (e < NE)           return 2.0f * xr[0]         - xr[NE - e];            // left pad
    if (e < NE + T_LEN)   return xr[e - NE];                                   // body
    return 2.0f * xr[T_LEN - 1] - xr[2 * T_LEN - 2 + NE - e];                  // right pad
}

__global__ void __launch_bounds__(THREADS, 2)
fir_bandpass_kernel(const float* __restrict__ x,
                    const float* __restrict__ h,
                    float* __restrict__ out)
{
    __shared__ float2 s2[S_ALLOC];   // interleaved row pair, extended signal (swizzled)
    __shared__ float2 h2[K_PAD];     // reversed taps duplicated into both lanes

    const int tid = threadIdx.x;
    const size_t row0 = (size_t)blockIdx.x * 2;
    const float* xr0 = x + row0 * T_LEN;
    const float* xr1 = xr0 + T_LEN;

    // Stage extended signal for both rows (swizzled store, conflict-free).
    for (int i = tid; i < S_ALLOC; i += THREADS) {
        float2 v = make_float2(0.0f, 0.0f);
        if (i < S_LEN) {
            int e = i + OFF;
            v.x = xext_val(xr0, e);
            v.y = xext_val(xr1, e);
        }
        s2[SW2(i)] = v;
    }
    // Stage reversed taps (no symmetry assumption).
    for (int k = tid; k < K_PAD; k += THREADS) {
        float hv = (k < NT) ? h[NT - 1 - k] : 0.0f;
        h2[k] = make_float2(hv, hv);
    }
    __syncthreads();

    const int t0 = tid * W;
    if (t0 < T_LEN) {
        const unsigned long long* su =
            reinterpret_cast<const unsigned long long*>(s2);
        const unsigned long long* hu =
            reinterpret_cast<const unsigned long long*>(h2);

        unsigned long long acc[W];
        unsigned long long w[W];
        #pragma unroll
        for (int r = 0; r < W; r++) acc[r] = 0ull;
        #pragma unroll
        for (int r = 0; r < W; r++) w[r] = su[SW2(t0 + r)];

        // Rolled outer loop (26 iters); inner fully unrolled.
        #pragma unroll 1
        for (int k = 0; k < K_PAD; k += W) {
            #pragma unroll
            for (int u = 0; u < W; u++) {
                unsigned long long hk = hu[k + u];
                // invariant: w[(u+r)&15] == s[t0 + k + u + r]
                #pragma unroll
                for (int r = 0; r < W; r++)
                    FMA_X2(acc[r], hk, w[(u + r) & (W - 1)], acc[r]);
                w[u] = su[SW2(t0 + k + u + W)];   // refill consumed slot
            }
        }

        float* o0 = out + row0 * T_LEN + t0;
        float* o1 = o0 + T_LEN;
        #pragma unroll
        for (int q = 0; q < W / 4; q++) {
            float2 a = *reinterpret_cast<float2*>(&acc[q * 4 + 0]);
            float2 b = *reinterpret_cast<float2*>(&acc[q * 4 + 1]);
            float2 c = *reinterpret_cast<float2*>(&acc[q * 4 + 2]);
            float2 d = *reinterpret_cast<float2*>(&acc[q * 4 + 3]);
            reinterpret_cast<float4*>(o0)[q] = make_float4(a.x, b.x, c.x, d.x);
            reinterpret_cast<float4*>(o1)[q] = make_float4(a.y, b.y, c.y, d.y);
        }
    }
}

extern "C" void kernel_launch(void* const* d_in, const int* in_sizes, int n_in,
                              void* d_out, int out_size)
{
    const float* x = (const float*)d_in[0];   // [64, 64, 4000] float32
    const float* h = (const float*)d_in[1];   // [413] float32
    float* out = (float*)d_out;               // [64, 64, 4000] float32

    fir_bandpass_kernel<<<NROWS / 2, THREADS>>>(x, h, out);
}

// round 3
// speedup vs baseline: 2.7673x; 1.1645x over previous
#include <cuda_runtime.h>
#include <cstdint>

typedef unsigned long long ull;

// Packed dual-FMA (Blackwell f32x2) — only reachable via PTX.
#define FMA_X2(d, a, b, c) \
    asm("fma.rn.f32x2 %0, %1, %2, %3;" : "=l"(d) : "l"(a), "l"(b), "l"(c))

constexpr int T_LEN  = 4000;   // samples per row
constexpr int NT     = 413;    // taps
constexpr int NE     = 412;    // n_edge
constexpr int OFF    = 206;    // x_ext base: out[t] = sum_k h_rev[k]*x_ext[t+206+k]
constexpr int S_LEN  = T_LEN + NT;        // 4413 valid staged samples
constexpr int S_LOG  = 4416;              // logical granules (multiple of 16)
constexpr int S_PHYS = S_LOG + S_LOG/16;  // 4692 padded granules
constexpr int K_PAD  = 416;               // taps padded to multiple of 16 (zeros)
constexpr int W      = 16;                // register window / outputs per thread
constexpr int THREADS = 256;
constexpr int NROWS  = 64 * 64;           // 4096 rows

// Pad-every-16 layout: logical granule g -> physical granule g + (g>>4).
// Lane stride of 16 logical granules -> 17 physical (8B units) -> conflict-free
// LDS.64; and since t0,k are multiples of 16, per-step addresses are
// base + u  (immediate offsets), base advancing by +17 per 16-tap block.
__device__ __forceinline__ int PAD(int g) { return g + (g >> 4); }

// reflect_limited extension value at x_ext index e, e in [206, 4618]
__device__ __forceinline__ float xext_val(const float* __restrict__ xr, int e) {
    if (e < NE)           return 2.0f * xr[0]         - xr[NE - e];            // left pad
    if (e < NE + T_LEN)   return xr[e - NE];                                   // body
    return 2.0f * xr[T_LEN - 1] - xr[2 * T_LEN - 2 + NE - e];                  // right pad
}

__global__ void __launch_bounds__(THREADS, 3)
fir_bandpass_kernel(const float* __restrict__ x,
                    const float* __restrict__ h,
                    float* __restrict__ out)
{
    __shared__ float2 s2[S_PHYS];    // interleaved row pair, extended signal (padded layout)
    __shared__ float2 h2[K_PAD];     // reversed taps duplicated into both lanes

    const int tid = threadIdx.x;
    const size_t row0 = (size_t)blockIdx.x * 2;
    const float* xr0 = x + row0 * T_LEN;
    const float* xr1 = xr0 + T_LEN;

    // Stage extended signal for both rows (padded store, conflict-free).
    for (int i = tid; i < S_LOG; i += THREADS) {
        float2 v = make_float2(0.0f, 0.0f);
        if (i < S_LEN) {
            int e = i + OFF;
            v.x = xext_val(xr0, e);
            v.y = xext_val(xr1, e);
        }
        s2[PAD(i)] = v;
    }
    // Stage reversed taps (no symmetry assumption).
    for (int k = tid; k < K_PAD; k += THREADS) {
        float hv = (k < NT) ? h[NT - 1 - k] : 0.0f;
        h2[k] = make_float2(hv, hv);
    }
    __syncthreads();

    const int t0 = tid * W;
    if (t0 < T_LEN) {
        const float2* wp = s2 + PAD(t0);   // window base (physical)
        const float2* rp = wp + 17;        // refill base for first k-block (= PAD(t0+16))
        const float2* hp = h2;

        ull acc[W];
        ull w[W];
        #pragma unroll
        for (int r = 0; r < W; r++) acc[r] = 0ull;
        #pragma unroll
        for (int r = 0; r < W; r++) w[r] = reinterpret_cast<const ull*>(wp)[r];

        // 26 k-blocks of 16 taps; inner fully unrolled, all LDS at imm offsets.
        #pragma unroll 1
        for (int kb = 0; kb < K_PAD / W; kb++) {
            #pragma unroll
            for (int u = 0; u < W; u++) {
                ull hk = reinterpret_cast<const ull*>(hp)[u];
                // invariant: w[(u+r)&15] == s[t0 + 16*kb + u + r]
                #pragma unroll
                for (int r = 0; r < W; r++)
                    FMA_X2(acc[r], hk, w[(u + r) & (W - 1)], acc[r]);
                w[u] = reinterpret_cast<const ull*>(rp)[u];   // refill consumed slot
            }
            rp += 17;   // +16 logical granules = +17 physical
            hp += 16;
        }

        float* o0 = out + row0 * T_LEN + t0;
        float* o1 = o0 + T_LEN;
        #pragma unroll
        for (int q = 0; q < W / 4; q++) {
            float2 a = *reinterpret_cast<float2*>(&acc[q * 4 + 0]);
            float2 b = *reinterpret_cast<float2*>(&acc[q * 4 + 1]);
            float2 c = *reinterpret_cast<float2*>(&acc[q * 4 + 2]);
            float2 d = *reinterpret_cast<float2*>(&acc[q * 4 + 3]);
            reinterpret_cast<float4*>(o0)[q] = make_float4(a.x, b.x, c.x, d.x);
            reinterpret_cast<float4*>(o1)[q] = make_float4(a.y, b.y, c.y, d.y);
        }
    }
}

extern "C" void kernel_launch(void* const* d_in, const int* in_sizes, int n_in,
                              void* d_out, int out_size)
{
    const float* x = (const float*)d_in[0];   // [64, 64, 4000] float32
    const float* h = (const float*)d_in[1];   // [413] float32
    float* out = (float*)d_out;               // [64, 64, 4000] float32

    fir_bandpass_kernel<<<NROWS / 2, THREADS>>>(x, h, out);
}

// round 5
// speedup vs baseline: 3.5283x; 1.2750x over previous
#include <cuda_runtime.h>
#include <cuda_bf16.h>
#include <cstdint>

typedef uint32_t u32;

// ====================== problem constants ======================
constexpr int T_LEN = 4000;
constexpr int NT    = 413;
constexpr int NE    = 412;
constexpr int OFF   = 206;              // xe[u] = x_ext[u + 206]
constexpr int S_LEN = T_LEN + NT;       // 4413
constexpr int NROWS = 4096;

constexpr int KTOT  = 576;              // K padded (need 539)
constexpr int KC    = 64;               // K chunk
constexpr int NCHUNK = KTOT / KC;       // 9
constexpr int XE_W  = T_LEN + KTOT;     // 4576
constexpr int MT    = 128;              // GEMM M (rows r)
constexpr int NTT   = 128;              // GEMM N (t positions)
constexpr int N_TTILE = (T_LEN + NTT - 1) / NTT;  // 32
constexpr int N_RBLK  = NROWS / MT;               // 32
constexpr int THREADS = 256;

// smem: 4 tiles (A_hi, A_lo, B_hi, B_lo) of 128 rows x 64 bf16, pitch 144B
constexpr int PITCHB     = 144;
constexpr int TILE_BYTES = 128 * PITCHB;        // 18432
constexpr int STAGE_BYTES = 4 * TILE_BYTES;     // 73728
constexpr int SMEM_DYN    = 2 * STAGE_BYTES;    // 147456

// ====================== device scratch ======================
__device__ __align__(16) __nv_bfloat16 g_xe_hi[(size_t)NROWS * XE_W];
__device__ __align__(16) __nv_bfloat16 g_xe_lo[(size_t)NROWS * XE_W];
__device__ __align__(16) __nv_bfloat16 g_B_hi[NTT * KTOT];
__device__ __align__(16) __nv_bfloat16 g_B_lo[NTT * KTOT];

// ====================== PTX helpers (family-agnostic, sm_80+) ======================
__device__ __forceinline__ u32 smem_u32(const void* p) {
    u32 a;
    asm("{ .reg .u64 t; cvta.to.shared.u64 t, %1; cvt.u32.u64 %0, t; }" : "=r"(a) : "l"(p));
    return a;
}
#define CP_ASYNC16(dst, src) \
    asm volatile("cp.async.cg.shared.global [%0], [%1], 16;" :: "r"(dst), "l"(src))
#define CP_COMMIT() asm volatile("cp.async.commit_group;" ::: "memory")

#define LDSM4(r, addr) \
    asm volatile("ldmatrix.sync.aligned.m8n8.x4.shared.b16 {%0,%1,%2,%3}, [%4];" \
        : "=r"((r)[0]), "=r"((r)[1]), "=r"((r)[2]), "=r"((r)[3]) : "r"(addr))

#define MMA16816(d, a, b) \
    asm volatile("mma.sync.aligned.m16n8k16.row.col.f32.bf16.bf16.f32 " \
        "{%0,%1,%2,%3}, {%4,%5,%6,%7}, {%8,%9}, {%0,%1,%2,%3};" \
        : "+f"((d)[0]), "+f"((d)[1]), "+f"((d)[2]), "+f"((d)[3]) \
        : "r"((a)[0]), "r"((a)[1]), "r"((a)[2]), "r"((a)[3]), \
          "r"((b)[0]), "r"((b)[1]))

// ====================== prep kernels ======================
__device__ __forceinline__ float xext_val(const float* __restrict__ xr, int e) {
    if (e < NE)         return 2.0f * xr[0]         - xr[NE - e];
    if (e < NE + T_LEN) return xr[e - NE];
    return 2.0f * xr[T_LEN - 1] - xr[2 * T_LEN - 2 + NE - e];
}
__device__ __forceinline__ void split_bf16(float v, __nv_bfloat16& hi, __nv_bfloat16& lo) {
    hi = __float2bfloat16(v);
    lo = __float2bfloat16(v - __bfloat162float(hi));
}

// Toeplitz B[n][k] = hrev[k-n] = h[412-(k-n)] for 0 <= k-n <= 412
__global__ void build_B_kernel(const float* __restrict__ h) {
    int idx = blockIdx.x * blockDim.x + threadIdx.x;
    if (idx >= NTT * KTOT) return;
    int n = idx / KTOT, k = idx % KTOT;
    int j = k - n;
    float v = (j >= 0 && j < NT) ? h[NT - 1 - j] : 0.0f;
    __nv_bfloat16 hi, lo;
    split_bf16(v, hi, lo);
    g_B_hi[idx] = hi;
    g_B_lo[idx] = lo;
}

__global__ void build_xe_kernel(const float* __restrict__ x) {
    int r = blockIdx.x;
    const float* xr = x + (size_t)r * T_LEN;
    size_t base = (size_t)r * XE_W;
    for (int u = threadIdx.x; u < XE_W; u += blockDim.x) {
        float v = (u < S_LEN) ? xext_val(xr, u + OFF) : 0.0f;
        __nv_bfloat16 hi, lo;
        split_bf16(v, hi, lo);
        g_xe_hi[base + u] = hi;
        g_xe_lo[base + u] = lo;
    }
}

// ====================== GEMM kernel (mma.sync / HMMA) ======================
__global__ void __launch_bounds__(THREADS, 1)
fir_gemm_kernel(float* __restrict__ out) {
    extern __shared__ __align__(1024) char smem[];
    const int tid = threadIdx.x;
    const int wid = tid >> 5;
    const int lid = tid & 31;
    const int wm  = wid & 3;        // 0..3 -> row slice of 32
    const int wn  = wid >> 2;       // 0..1 -> t slice of 64
    const int t0    = blockIdx.x * NTT;
    const int rbase = blockIdx.y * MT;

    const u32 sb = smem_u32(smem);

    // ---- staging: chunk c (k = c*64 .. +63) into stage s ----
    auto stage = [&](int c, int s) {
        const int kg = c * KC;
        const u32 dbase = sb + s * STAGE_BYTES;
        #pragma unroll
        for (int it = 0; it < 16; it++) {
            int idx = it * THREADS + tid;       // 0..4095
            int row = idx >> 3;                 // 0..511
            int seg = idx & 7;                  // 16B segment within 128B row
            int cls = row >> 7;                 // 0:Ahi 1:Alo 2:Bhi 3:Blo
            int r   = row & 127;
            const __nv_bfloat16* g;
            size_t goff;
            if (cls < 2) {
                g = cls ? g_xe_lo : g_xe_hi;
                goff = (size_t)(rbase + r) * XE_W + (t0 + kg) + seg * 8;
            } else {
                g = (cls == 3) ? g_B_lo : g_B_hi;
                goff = (size_t)r * KTOT + kg + seg * 8;
            }
            u32 dst = dbase + cls * TILE_BYTES + r * PITCHB + seg * 16;
            CP_ASYNC16(dst, (const char*)(g + goff));
        }
    };

    // ---- per-thread ldmatrix base addresses (stage 0) ----
    // A tile i (m16), hi/lo: row = wm*32 + i*16 + (lid&15); colbyte = (lid>>4)*16 (+ks*32)
    u32 aAddr[2][2];
    #pragma unroll
    for (int v = 0; v < 2; v++)
        #pragma unroll
        for (int i = 0; i < 2; i++)
            aAddr[v][i] = sb + v * TILE_BYTES +
                          (wm * 32 + i * 16 + (lid & 15)) * PITCHB + ((lid >> 4) * 16);
    // B pair jp (2 n8-tiles), hi/lo: nrow = wn*64 + jp*16 + (lid>>4)*8 + (lid&7);
    //   colbyte = ((lid>>3)&1)*16 (+ks*32)
    u32 bAddr[2][4];
    #pragma unroll
    for (int v = 0; v < 2; v++)
        #pragma unroll
        for (int jp = 0; jp < 4; jp++)
            bAddr[v][jp] = sb + (2 + v) * TILE_BYTES +
                           (wn * 64 + jp * 16 + ((lid >> 4) * 8) + (lid & 7)) * PITCHB +
                           (((lid >> 3) & 1) * 16);

    float acc[2][8][4];
    #pragma unroll
    for (int i = 0; i < 2; i++)
        #pragma unroll
        for (int j = 0; j < 8; j++)
            #pragma unroll
            for (int q = 0; q < 4; q++) acc[i][j][q] = 0.0f;

    stage(0, 0);
    CP_COMMIT();

    #pragma unroll 1
    for (int c = 0; c < NCHUNK; c++) {
        const int s = c & 1;
        if (c + 1 < NCHUNK) {
            stage(c + 1, s ^ 1);
            CP_COMMIT();
            asm volatile("cp.async.wait_group 1;" ::: "memory");
        } else {
            asm volatile("cp.async.wait_group 0;" ::: "memory");
        }
        __syncthreads();

        const u32 soff = s * STAGE_BYTES;
        #pragma unroll
        for (int ks = 0; ks < KC / 16; ks++) {
            const u32 kb = soff + ks * 32;
            u32 ah[2][4], al[2][4];         // A frags (hi, lo) per m-tile
            u32 bh[8][2], bl[8][2];         // B frags per n8-tile
            #pragma unroll
            for (int i = 0; i < 2; i++) {
                LDSM4(ah[i], aAddr[0][i] + kb);
                LDSM4(al[i], aAddr[1][i] + kb);
            }
            #pragma unroll
            for (int jp = 0; jp < 4; jp++) {
                u32 r4[4];
                LDSM4(r4, bAddr[0][jp] + kb);
                bh[jp*2][0] = r4[0]; bh[jp*2][1] = r4[1];
                bh[jp*2+1][0] = r4[2]; bh[jp*2+1][1] = r4[3];
                LDSM4(r4, bAddr[1][jp] + kb);
                bl[jp*2][0] = r4[0]; bl[jp*2][1] = r4[1];
                bl[jp*2+1][0] = r4[2]; bl[jp*2+1][1] = r4[3];
            }
            // term 0: hi*hi; term 1: hi*lo; term 2: lo*hi (acc reuse distance 16)
            #pragma unroll
            for (int i = 0; i < 2; i++)
                #pragma unroll
                for (int j = 0; j < 8; j++) MMA16816(acc[i][j], ah[i], bh[j]);
            #pragma unroll
            for (int i = 0; i < 2; i++)
                #pragma unroll
                for (int j = 0; j < 8; j++) MMA16816(acc[i][j], ah[i], bl[j]);
            #pragma unroll
            for (int i = 0; i < 2; i++)
                #pragma unroll
                for (int j = 0; j < 8; j++) MMA16816(acc[i][j], al[i], bh[j]);
        }
        __syncthreads();   // protect buffer s before it is restaged next iter
    }

    // ---- epilogue: D[m=r][n=t] fragments -> out[r*T_LEN + t] ----
    #pragma unroll
    for (int i = 0; i < 2; i++) {
        int r0 = rbase + wm * 32 + i * 16 + (lid >> 2);
        #pragma unroll
        for (int j = 0; j < 8; j++) {
            int t = t0 + wn * 64 + j * 8 + 2 * (lid & 3);
            if (t < T_LEN) {
                *reinterpret_cast<float2*>(out + (size_t)r0 * T_LEN + t) =
                    make_float2(acc[i][j][0], acc[i][j][1]);
                *reinterpret_cast<float2*>(out + (size_t)(r0 + 8) * T_LEN + t) =
                    make_float2(acc[i][j][2], acc[i][j][3]);
            }
        }
    }
}

// ====================== launch ======================
extern "C" void kernel_launch(void* const* d_in, const int* in_sizes, int n_in,
                              void* d_out, int out_size)
{
    const float* x = (const float*)d_in[0];   // [64, 64, 4000] f32
    const float* h = (const float*)d_in[1];   // [413] f32
    float* out = (float*)d_out;

    cudaFuncSetAttribute(fir_gemm_kernel,
                         cudaFuncAttributeMaxDynamicSharedMemorySize, SMEM_DYN);

    build_B_kernel<<<(NTT * KTOT + 255) / 256, 256>>>(h);
    build_xe_kernel<<<NROWS, 256>>>(x);
    fir_gemm_kernel<<<dim3(N_TTILE, N_RBLK), THREADS, SMEM_DYN>>>(out);
}

// round 6
// speedup vs baseline: 7.0240x; 1.9908x over previous
#include <cuda_runtime.h>
#include <cuda_fp16.h>
#include <cstdint>

typedef uint32_t u32;

// ====================== problem constants ======================
constexpr int T_LEN = 4000;
constexpr int NT    = 413;
constexpr int NE    = 412;
constexpr int OFF   = 206;              // xe[u] = x_ext[u + 206]
constexpr int S_LEN = T_LEN + NT;       // 4413
constexpr int NROWS = 4096;

constexpr int KTOT  = 576;              // K padded (need 540)
constexpr int KC    = 64;               // K chunk
constexpr int NCHUNK = KTOT / KC;       // 9
constexpr int XE_W  = T_LEN + KTOT;     // 4576
constexpr int MT    = 128;              // GEMM M (rows r)
constexpr int NTT   = 128;              // GEMM N (t positions)
constexpr int N_TTILE = (T_LEN + NTT - 1) / NTT;  // 32
constexpr int N_RBLK  = NROWS / MT;               // 32
constexpr int THREADS = 256;

constexpr float H_SCALE = 512.0f;       // keep fp16 taps normal-range
constexpr float INV_H_SCALE = 1.0f / 512.0f;

// smem: 2 tiles (A = xe rows, B = Toeplitz) of 128 rows x 64 fp16, pitch 144B
constexpr int PITCHB      = 144;
constexpr int TILE_BYTES  = 128 * PITCHB;       // 18432
constexpr int STAGE_BYTES = 2 * TILE_BYTES;     // 36864
constexpr int SMEM_DYN    = 2 * STAGE_BYTES;    // 73728

// ====================== device scratch ======================
__device__ __align__(16) __half g_xe[(size_t)NROWS * XE_W];
__device__ __align__(16) __half g_B[NTT * KTOT];

// ====================== PTX helpers (family-agnostic, sm_80+) ======================
__device__ __forceinline__ u32 smem_u32(const void* p) {
    u32 a;
    asm("{ .reg .u64 t; cvta.to.shared.u64 t, %1; cvt.u32.u64 %0, t; }" : "=r"(a) : "l"(p));
    return a;
}
#define CP_ASYNC16(dst, src) \
    asm volatile("cp.async.cg.shared.global [%0], [%1], 16;" :: "r"(dst), "l"(src))
#define CP_COMMIT() asm volatile("cp.async.commit_group;" ::: "memory")

#define LDSM4(r, addr) \
    asm volatile("ldmatrix.sync.aligned.m8n8.x4.shared.b16 {%0,%1,%2,%3}, [%4];" \
        : "=r"((r)[0]), "=r"((r)[1]), "=r"((r)[2]), "=r"((r)[3]) : "r"(addr))

#define MMA16816(d, a, b) \
    asm volatile("mma.sync.aligned.m16n8k16.row.col.f32.f16.f16.f32 " \
        "{%0,%1,%2,%3}, {%4,%5,%6,%7}, {%8,%9}, {%0,%1,%2,%3};" \
        : "+f"((d)[0]), "+f"((d)[1]), "+f"((d)[2]), "+f"((d)[3]) \
        : "r"((a)[0]), "r"((a)[1]), "r"((a)[2]), "r"((a)[3]), \
          "r"((b)[0]), "r"((b)[1]))

// ====================== prep kernels ======================
__device__ __forceinline__ float xext_val(const float* __restrict__ xr, int e) {
    if (e < NE)         return 2.0f * xr[0]         - xr[NE - e];
    if (e < NE + T_LEN) return xr[e - NE];
    return 2.0f * xr[T_LEN - 1] - xr[2 * T_LEN - 2 + NE - e];
}

// Toeplitz B[n][k] = hrev[k-n] * H_SCALE, hrev[j] = h[412-j] for j in [0,413)
__global__ void build_B_kernel(const float* __restrict__ h) {
    int idx = blockIdx.x * blockDim.x + threadIdx.x;
    if (idx >= NTT * KTOT) return;
    int n = idx / KTOT, k = idx % KTOT;
    int j = k - n;
    float v = (j >= 0 && j < NT) ? h[NT - 1 - j] * H_SCALE : 0.0f;
    g_B[idx] = __float2half(v);
}

__global__ void build_xe_kernel(const float* __restrict__ x) {
    int r = blockIdx.x;
    const float* xr = x + (size_t)r * T_LEN;
    size_t base = (size_t)r * XE_W;
    for (int u = threadIdx.x; u < XE_W; u += blockDim.x) {
        float v = (u < S_LEN) ? xext_val(xr, u + OFF) : 0.0f;
        g_xe[base + u] = __float2half(v);
    }
}

// ====================== GEMM kernel (mma.sync fp16, single term) ======================
__global__ void __launch_bounds__(THREADS, 2)
fir_gemm_kernel(float* __restrict__ out) {
    extern __shared__ __align__(1024) char smem[];
    const int tid = threadIdx.x;
    const int wid = tid >> 5;
    const int lid = tid & 31;
    const int wm  = wid & 3;        // 0..3 -> row slice of 32
    const int wn  = wid >> 2;       // 0..1 -> t slice of 64
    const int t0    = blockIdx.x * NTT;
    const int rbase = blockIdx.y * MT;

    const u32 sb = smem_u32(smem);

    // ---- staging: chunk c (k = c*64 .. +63) into stage s ----
    auto stage = [&](int c, int s) {
        const int kg = c * KC;
        const u32 dbase = sb + s * STAGE_BYTES;
        #pragma unroll
        for (int it = 0; it < 8; it++) {
            int idx = it * THREADS + tid;       // 0..2047
            int cls = idx >> 10;                // 0: A (xe), 1: B (Toeplitz)
            int q   = idx & 1023;
            int r   = q >> 3;                   // 0..127
            int seg = q & 7;                    // 16B segment within 128B row
            const __half* g;
            size_t goff;
            if (cls == 0) {
                g = g_xe;
                goff = (size_t)(rbase + r) * XE_W + (t0 + kg) + seg * 8;
            } else {
                g = g_B;
                goff = (size_t)r * KTOT + kg + seg * 8;
            }
            u32 dst = dbase + cls * TILE_BYTES + r * PITCHB + seg * 16;
            CP_ASYNC16(dst, (const char*)(g + goff));
        }
    };

    // ---- per-thread ldmatrix base addresses (stage 0) ----
    // A tile i (m16): row = wm*32 + i*16 + (lid&15); colbyte = (lid>>4)*16 (+ks*32)
    u32 aAddr[2];
    #pragma unroll
    for (int i = 0; i < 2; i++)
        aAddr[i] = sb + (wm * 32 + i * 16 + (lid & 15)) * PITCHB + ((lid >> 4) * 16);
    // B pair jp (2 n8-tiles): nrow = wn*64 + jp*16 + (lid>>4)*8 + (lid&7);
    //   colbyte = ((lid>>3)&1)*16 (+ks*32)
    u32 bAddr[4];
    #pragma unroll
    for (int jp = 0; jp < 4; jp++)
        bAddr[jp] = sb + TILE_BYTES +
                    (wn * 64 + jp * 16 + ((lid >> 4) * 8) + (lid & 7)) * PITCHB +
                    (((lid >> 3) & 1) * 16);

    float acc[2][8][4];
    #pragma unroll
    for (int i = 0; i < 2; i++)
        #pragma unroll
        for (int j = 0; j < 8; j++)
            #pragma unroll
            for (int q = 0; q < 4; q++) acc[i][j][q] = 0.0f;

    stage(0, 0);
    CP_COMMIT();

    #pragma unroll 1
    for (int c = 0; c < NCHUNK; c++) {
        const int s = c & 1;
        if (c + 1 < NCHUNK) {
            stage(c + 1, s ^ 1);
            CP_COMMIT();
            asm volatile("cp.async.wait_group 1;" ::: "memory");
        } else {
            asm volatile("cp.async.wait_group 0;" ::: "memory");
        }
        __syncthreads();

        const u32 soff = s * STAGE_BYTES;
        #pragma unroll
        for (int ks = 0; ks < KC / 16; ks++) {
            const u32 kb = soff + ks * 32;
            u32 a[2][4];
            u32 b[8][2];
            #pragma unroll
            for (int i = 0; i < 2; i++) LDSM4(a[i], aAddr[i] + kb);
            #pragma unroll
            for (int jp = 0; jp < 4; jp++) {
                u32 r4[4];
                LDSM4(r4, bAddr[jp] + kb);
                b[jp*2][0]   = r4[0]; b[jp*2][1]   = r4[1];
                b[jp*2+1][0] = r4[2]; b[jp*2+1][1] = r4[3];
            }
            #pragma unroll
            for (int i = 0; i < 2; i++)
                #pragma unroll
                for (int j = 0; j < 8; j++) MMA16816(acc[i][j], a[i], b[j]);
        }
        __syncthreads();   // protect buffer s before restage next iter
    }

    // ---- epilogue: D[m=r][n=t] -> out[r*T_LEN + t], undo H_SCALE ----
    #pragma unroll
    for (int i = 0; i < 2; i++) {
        int r0 = rbase + wm * 32 + i * 16 + (lid >> 2);
        #pragma unroll
        for (int j = 0; j < 8; j++) {
            int t = t0 + wn * 64 + j * 8 + 2 * (lid & 3);
            if (t < T_LEN) {
                *reinterpret_cast<float2*>(out + (size_t)r0 * T_LEN + t) =
                    make_float2(acc[i][j][0] * INV_H_SCALE, acc[i][j][1] * INV_H_SCALE);
                *reinterpret_cast<float2*>(out + (size_t)(r0 + 8) * T_LEN + t) =
                    make_float2(acc[i][j][2] * INV_H_SCALE, acc[i][j][3] * INV_H_SCALE);
            }
        }
    }
}

// ====================== launch ======================
extern "C" void kernel_launch(void* const* d_in, const int* in_sizes, int n_in,
                              void* d_out, int out_size)
{
    const float* x = (const float*)d_in[0];   // [64, 64, 4000] f32
    const float* h = (const float*)d_in[1];   // [413] f32
    float* out = (float*)d_out;

    cudaFuncSetAttribute(fir_gemm_kernel,
                         cudaFuncAttributeMaxDynamicSharedMemorySize, SMEM_DYN);

    build_B_kernel<<<(NTT * KTOT + 255) / 256, 256>>>(h);
    build_xe_kernel<<<NROWS, 256>>>(x);
    fir_gemm_kernel<<<dim3(N_TTILE, N_RBLK), THREADS, SMEM_DYN>>>(out);
}

// round 7
// speedup vs baseline: 8.3809x; 1.1932x over previous
#include <cuda_runtime.h>
#include <cuda_fp16.h>
#include <cstdint>

typedef uint32_t u32;

// ====================== problem constants ======================
constexpr int T_LEN = 4000;
constexpr int NT    = 413;
constexpr int NE    = 412;
constexpr int OFF   = 206;              // xe[u] = x_ext[u + 206]
constexpr int S_LEN = T_LEN + NT;       // 4413
constexpr int NROWS = 4096;

constexpr int KTOT  = 576;              // K padded (need 540)
constexpr int KC    = 64;               // K chunk
constexpr int NCHUNK = KTOT / KC;       // 9
constexpr int XE_W  = T_LEN + KTOT;     // 4576
constexpr int MT    = 128;              // GEMM M (rows r)
constexpr int NTT   = 128;              // GEMM N (t positions)
constexpr int N_TTILE = (T_LEN + NTT - 1) / NTT;  // 32
constexpr int N_RBLK  = NROWS / MT;               // 32
constexpr int THREADS = 256;

constexpr float H_SCALE = 512.0f;       // keep fp16 taps normal-range
constexpr float INV_H_SCALE = 1.0f / 512.0f;

// smem: 2 tiles (A = xe rows, B = Toeplitz) of 128 rows x 64 fp16, pitch 144B
constexpr int PITCHB      = 144;
constexpr int TILE_BYTES  = 128 * PITCHB;       // 18432
constexpr int STAGE_BYTES = 2 * TILE_BYTES;     // 36864
constexpr int SMEM_DYN    = 2 * STAGE_BYTES;    // 73728

// ====================== device scratch ======================
__device__ __align__(16) __half g_xe[(size_t)NROWS * XE_W];
__device__ __align__(16) __half g_B[NTT * KTOT];

// ====================== PTX helpers (family-agnostic, sm_80+) ======================
__device__ __forceinline__ u32 smem_u32(const void* p) {
    u32 a;
    asm("{ .reg .u64 t; cvta.to.shared.u64 t, %1; cvt.u32.u64 %0, t; }" : "=r"(a) : "l"(p));
    return a;
}
#define CP_ASYNC16(dst, src) \
    asm volatile("cp.async.cg.shared.global [%0], [%1], 16;" :: "r"(dst), "l"(src))
#define CP_COMMIT() asm volatile("cp.async.commit_group;" ::: "memory")

#define LDSM4(r, addr) \
    asm volatile("ldmatrix.sync.aligned.m8n8.x4.shared.b16 {%0,%1,%2,%3}, [%4];" \
        : "=r"((r)[0]), "=r"((r)[1]), "=r"((r)[2]), "=r"((r)[3]) : "r"(addr))

#define MMA16816(d, a, b) \
    asm volatile("mma.sync.aligned.m16n8k16.row.col.f32.f16.f16.f32 " \
        "{%0,%1,%2,%3}, {%4,%5,%6,%7}, {%8,%9}, {%0,%1,%2,%3};" \
        : "+f"((d)[0]), "+f"((d)[1]), "+f"((d)[2]), "+f"((d)[3]) \
        : "r"((a)[0]), "r"((a)[1]), "r"((a)[2]), "r"((a)[3]), \
          "r"((b)[0]), "r"((b)[1]))

// ====================== fused prep kernel ======================
__device__ __forceinline__ float xext_val(const float* __restrict__ xr, int e) {
    if (e < NE)         return 2.0f * xr[0]         - xr[NE - e];
    if (e < NE + T_LEN) return xr[e - NE];
    return 2.0f * xr[T_LEN - 1] - xr[2 * T_LEN - 2 + NE - e];
}

// blocks [0, NROWS): xe row build with 16B stores.
// blocks [NROWS, NROWS+288): Toeplitz B[n][k] = hrev[k-n] * H_SCALE.
__global__ void prep_kernel(const float* __restrict__ x, const float* __restrict__ h) {
    const int b = blockIdx.x;
    if (b < NROWS) {
        const float* xr = x + (size_t)b * T_LEN;
        __half* dst = g_xe + (size_t)b * XE_W;
        for (int seg = threadIdx.x; seg < XE_W / 8; seg += blockDim.x) {
            const int u0 = seg * 8;
            __half hv[8];
            #pragma unroll
            for (int q = 0; q < 8; q++) {
                int u = u0 + q;
                float v = (u < S_LEN) ? xext_val(xr, u + OFF) : 0.0f;
                hv[q] = __float2half(v);
            }
            *reinterpret_cast<uint4*>(dst + u0) = *reinterpret_cast<const uint4*>(hv);
        }
    } else {
        int idx = (b - NROWS) * blockDim.x + threadIdx.x;
        if (idx < NTT * KTOT) {
            int n = idx / KTOT, k = idx % KTOT;
            int j = k - n;
            float v = (j >= 0 && j < NT) ? h[NT - 1 - j] * H_SCALE : 0.0f;
            g_B[idx] = __float2half(v);
        }
    }
}
constexpr int PREP_B_BLOCKS = (NTT * KTOT + 255) / 256;   // 288

// ====================== GEMM kernel (mma.sync fp16, single term) ======================
__global__ void __launch_bounds__(THREADS, 2)
fir_gemm_kernel(float* __restrict__ out) {
    extern __shared__ __align__(1024) char smem[];
    const int tid = threadIdx.x;
    const int wid = tid >> 5;
    const int lid = tid & 31;
    const int wm  = wid & 3;        // 0..3 -> row slice of 32
    const int wn  = wid >> 2;       // 0..1 -> t slice of 64
    const int t0    = blockIdx.x * NTT;
    const int rbase = blockIdx.y * MT;

    // Toeplitz band: warp-group wn's B rows (n in [wn*64, wn*64+64)) are
    // entirely zero in one chunk: wn=0 -> chunk 8 (k>=512 => k-n>412),
    // wn=1 -> chunk 0 (k<64<=n => k-n<0). Skip its MMAs exactly.
    const int skipc = (wn == 0) ? (NCHUNK - 1) : 0;

    const u32 sb = smem_u32(smem);

    // ---- staging: chunk c (k = c*64 .. +63) into stage s ----
    auto stage = [&](int c, int s) {
        const int kg = c * KC;
        const u32 dbase = sb + s * STAGE_BYTES;
        #pragma unroll
        for (int it = 0; it < 8; it++) {
            int idx = it * THREADS + tid;       // 0..2047
            int cls = idx >> 10;                // 0: A (xe), 1: B (Toeplitz)
            int q   = idx & 1023;
            int r   = q >> 3;                   // 0..127
            int seg = q & 7;                    // 16B segment within 128B row
            const __half* g;
            size_t goff;
            if (cls == 0) {
                g = g_xe;
                goff = (size_t)(rbase + r) * XE_W + (t0 + kg) + seg * 8;
            } else {
                g = g_B;
                goff = (size_t)r * KTOT + kg + seg * 8;
            }
            u32 dst = dbase + cls * TILE_BYTES + r * PITCHB + seg * 16;
            CP_ASYNC16(dst, (const char*)(g + goff));
        }
    };

    // ---- per-thread ldmatrix base addresses (stage 0) ----
    u32 aAddr[2];
    #pragma unroll
    for (int i = 0; i < 2; i++)
        aAddr[i] = sb + (wm * 32 + i * 16 + (lid & 15)) * PITCHB + ((lid >> 4) * 16);
    u32 bAddr[4];
    #pragma unroll
    for (int jp = 0; jp < 4; jp++)
        bAddr[jp] = sb + TILE_BYTES +
                    (wn * 64 + jp * 16 + ((lid >> 4) * 8) + (lid & 7)) * PITCHB +
                    (((lid >> 3) & 1) * 16);

    float acc[2][8][4];
    #pragma unroll
    for (int i = 0; i < 2; i++)
        #pragma unroll
        for (int j = 0; j < 8; j++)
            #pragma unroll
            for (int q = 0; q < 4; q++) acc[i][j][q] = 0.0f;

    stage(0, 0);
    CP_COMMIT();

    #pragma unroll 1
    for (int c = 0; c < NCHUNK; c++) {
        const int s = c & 1;
        if (c + 1 < NCHUNK) {
            stage(c + 1, s ^ 1);
            CP_COMMIT();
            asm volatile("cp.async.wait_group 1;" ::: "memory");
        } else {
            asm volatile("cp.async.wait_group 0;" ::: "memory");
        }
        __syncthreads();

        if (c != skipc) {
            const u32 soff = s * STAGE_BYTES;
            #pragma unroll
            for (int ks = 0; ks < KC / 16; ks++) {
                const u32 kb = soff + ks * 32;
                u32 a[2][4];
                u32 b[8][2];
                #pragma unroll
                for (int i = 0; i < 2; i++) LDSM4(a[i], aAddr[i] + kb);
                #pragma unroll
                for (int jp = 0; jp < 4; jp++) {
                    u32 r4[4];
                    LDSM4(r4, bAddr[jp] + kb);
                    b[jp*2][0]   = r4[0]; b[jp*2][1]   = r4[1];
                    b[jp*2+1][0] = r4[2]; b[jp*2+1][1] = r4[3];
                }
                #pragma unroll
                for (int i = 0; i < 2; i++)
                    #pragma unroll
                    for (int j = 0; j < 8; j++) MMA16816(acc[i][j], a[i], b[j]);
            }
        }
        __syncthreads();   // protect buffer s before restage next iter
    }

    // ---- epilogue: D[m=r][n=t] -> out[r*T_LEN + t], undo H_SCALE ----
    #pragma unroll
    for (int i = 0; i < 2; i++) {
        int r0 = rbase + wm * 32 + i * 16 + (lid >> 2);
        #pragma unroll
        for (int j = 0; j < 8; j++) {
            int t = t0 + wn * 64 + j * 8 + 2 * (lid & 3);
            if (t < T_LEN) {
                *reinterpret_cast<float2*>(out + (size_t)r0 * T_LEN + t) =
                    make_float2(acc[i][j][0] * INV_H_SCALE, acc[i][j][1] * INV_H_SCALE);
                *reinterpret_cast<float2*>(out + (size_t)(r0 + 8) * T_LEN + t) =
                    make_float2(acc[i][j][2] * INV_H_SCALE, acc[i][j][3] * INV_H_SCALE);
            }
        }
    }
}

// ====================== launch ======================
extern "C" void kernel_launch(void* const* d_in, const int* in_sizes, int n_in,
                              void* d_out, int out_size)
{
    const float* x = (const float*)d_in[0];   // [64, 64, 4000] f32
    const float* h = (const float*)d_in[1];   // [413] f32
    float* out = (float*)d_out;

    cudaFuncSetAttribute(fir_gemm_kernel,
                         cudaFuncAttributeMaxDynamicSharedMemorySize, SMEM_DYN);

    prep_kernel<<<NROWS + PREP_B_BLOCKS, 256>>>(x, h);
    fir_gemm_kernel<<<dim3(N_TTILE, N_RBLK), THREADS, SMEM_DYN>>>(out);
}